// round 12
// baseline (speedup 1.0000x reference)
#include <cuda_runtime.h>
#include <cstdint>
#include <math.h>

#define B_ROWS   262144
#define STEPS    10
#define NTHREADS 256
#define N_ELEM   33554432u    // B_ROWS*128 = 2^25

__device__ double g_sum;
__device__ float  g_noise_scale;
__device__ float  g_noise[(size_t)STEPS * N_ELEM];  // unscaled normals, 1.34 GB
__device__ float  g_X[N_ELEM];                      // exact state between steps
__device__ uint32_t g_bfrag[256 * 32];              // per-thread-identity J frags

// ---- phase1 SMEM layout ----
#define XT_ROW 164
#define XT_CLS 40
#define PL_ROW 132
#define P1_XT  0
#define P1_XST (64*XT_ROW)
#define P1_WORDS (P1_XST + 64*PL_ROW)
#define P1_SMEM (P1_WORDS*4)

// ---- langevin XT layout (words) ----
#define CSP  20
#define ROWP 80

// ---------------------------------------------------------------------------
// MMA helpers
// ---------------------------------------------------------------------------
__device__ __forceinline__ uint32_t f2tf32(float f) {
    uint32_t r;
    asm("cvt.rna.tf32.f32 %0, %1;" : "=r"(r) : "f"(f));
    return r;
}
__device__ __forceinline__ void mma_tf32(float d[4], const uint32_t a[4],
                                         const uint32_t b[2]) {
    asm volatile(
        "mma.sync.aligned.m16n8k8.row.col.f32.tf32.tf32.f32 "
        "{%0,%1,%2,%3}, {%4,%5,%6,%7}, {%8,%9}, {%0,%1,%2,%3};\n"
        : "+f"(d[0]), "+f"(d[1]), "+f"(d[2]), "+f"(d[3])
        : "r"(a[0]), "r"(a[1]), "r"(a[2]), "r"(a[3]), "r"(b[0]), "r"(b[1]));
}
__device__ __forceinline__ void mma_bf16(float d[4], const uint32_t a[4],
                                         const uint32_t b[2]) {
    asm volatile(
        "mma.sync.aligned.m16n8k16.row.col.f32.bf16.bf16.f32 "
        "{%0,%1,%2,%3}, {%4,%5,%6,%7}, {%8,%9}, {%0,%1,%2,%3};\n"
        : "+f"(d[0]), "+f"(d[1]), "+f"(d[2]), "+f"(d[3])
        : "r"(a[0]), "r"(a[1]), "r"(a[2]), "r"(a[3]), "r"(b[0]), "r"(b[1]));
}
__device__ __forceinline__ uint32_t pack_bf16(float hi, float lo) {
    uint32_t r;
    asm("cvt.rn.bf16x2.f32 %0, %1, %2;" : "=r"(r) : "f"(hi), "f"(lo));
    return r;
}
__device__ __forceinline__ float tanh_fast(float x) {
    float r;
    asm("tanh.approx.f32 %0, %1;" : "=f"(r) : "f"(x));
    return r;
}
__device__ __forceinline__ uint32_t imad1(uint32_t a, uint32_t one, uint32_t b) {
    uint32_t r;
    asm("mad.lo.u32 %0, %1, %2, %3;" : "=r"(r) : "r"(a), "r"(one), "r"(b));
    return r;
}

// ---------------------------------------------------------------------------
// Threefry-2x32/20
// ---------------------------------------------------------------------------
__host__ __forceinline__ void threefry_host(
    uint32_t k0, uint32_t k1, uint32_t x0, uint32_t x1,
    uint32_t& o0, uint32_t& o1)
{
    uint32_t ks0 = k0, ks1 = k1, ks2 = k0 ^ k1 ^ 0x1BD11BDAu;
    x0 += ks0; x1 += ks1;
#define TF_R(r) { x0 += x1; x1 = (x1 << (r)) | (x1 >> (32 - (r))); x1 ^= x0; }
    TF_R(13) TF_R(15) TF_R(26) TF_R(6)
    x0 += ks1; x1 += ks2 + 1u;
    TF_R(17) TF_R(29) TF_R(16) TF_R(24)
    x0 += ks2; x1 += ks0 + 2u;
    TF_R(13) TF_R(15) TF_R(26) TF_R(6)
    x0 += ks0; x1 += ks1 + 3u;
    TF_R(17) TF_R(29) TF_R(16) TF_R(24)
    x0 += ks1; x1 += ks2 + 4u;
    TF_R(13) TF_R(15) TF_R(26) TF_R(6)
    x0 += ks2; x1 += ks0 + 5u;
#undef TF_R
    o0 = x0; o1 = x1;
}

__device__ __forceinline__ uint32_t rnd_bits(uint32_t one,
    uint32_t k0, uint32_t k1, uint32_t idx)
{
    uint32_t ks2 = k0 ^ k1 ^ 0x1BD11BDAu;
    uint32_t x0 = k0;
    uint32_t x1 = idx + k1;
#define TF_B(r) { x0 = imad1(x0, one, x1); x1 = __funnelshift_l(x1, x1, r); x1 ^= x0; }
    TF_B(13) TF_B(15) TF_B(26) TF_B(6)
    x0 = imad1(x0, one, k1);  x1 += ks2 + 1u;
    TF_B(17) TF_B(29) TF_B(16) TF_B(24)
    x0 = imad1(x0, one, ks2); x1 += k0 + 2u;
    TF_B(13) TF_B(15) TF_B(26) TF_B(6)
    x0 = imad1(x0, one, k0);  x1 += k1 + 3u;
    TF_B(17) TF_B(29) TF_B(16) TF_B(24)
    x0 = imad1(x0, one, k1);  x1 += ks2 + 4u;
    TF_B(13) TF_B(15) TF_B(26) TF_B(6)
    x0 = imad1(x0, one, ks2); x1 += k0 + 5u;
#undef TF_B
    return x0 ^ x1;
}

__device__ __forceinline__ float bits_to_normal(uint32_t bits)
{
    const float lo = -0.99999994f;
    float u = __uint_as_float((bits >> 9) | 0x3f800000u) - 1.0f;
    float x = fmaf(u, 2.0f, lo);
    x = fmaxf(x, lo);
    float w = -__logf(fmaf(-x, x, 1.0f));
    float p;
    if (w < 5.0f) {
        w -= 2.5f;
        p = 2.81022636e-08f;
        p = fmaf(p, w, 3.43273939e-07f);
        p = fmaf(p, w, -3.5233877e-06f);
        p = fmaf(p, w, -4.39150654e-06f);
        p = fmaf(p, w, 0.00021858087f);
        p = fmaf(p, w, -0.00125372503f);
        p = fmaf(p, w, -0.00417768164f);
        p = fmaf(p, w, 0.246640727f);
        p = fmaf(p, w, 1.50140941f);
    } else {
        w = sqrtf(w) - 3.0f;
        p = -0.000200214257f;
        p = fmaf(p, w, 0.000100950558f);
        p = fmaf(p, w, 0.00134934322f);
        p = fmaf(p, w, -0.00367342844f);
        p = fmaf(p, w, 0.00573950773f);
        p = fmaf(p, w, -0.0076224613f);
        p = fmaf(p, w, 0.00943887047f);
        p = fmaf(p, w, 1.00167406f);
        p = fmaf(p, w, 2.83297682f);
    }
    return 1.41421354f * (p * x);
}

struct Keys { uint32_t k0[STEPS]; uint32_t k1[STEPS]; uint32_t one; };

__global__ void zero_kernel() { g_sum = 0.0; }
__global__ void finalize_kernel()
{
    double mean = g_sum * (1.0 / 33554432.0);
    float temp = 0.1f * (1.0f + (float)mean * 10.0f);
    g_noise_scale = sqrtf(2.0f * 0.1f * temp);
}

// ===========================================================================
// Noise, one step per launch: UNSCALED normals (no finalize dependency)
// ===========================================================================
__global__ void __launch_bounds__(NTHREADS) noise_step(Keys keys, int s)
{
    uint32_t t = blockIdx.x * NTHREADS + threadIdx.x;  // 2^23 threads
    uint32_t idx = t * 4u;
    uint32_t k0 = keys.k0[s], k1 = keys.k1[s], one = keys.one;
    uint32_t b0 = rnd_bits(one, k0, k1, idx);
    uint32_t b1 = rnd_bits(one, k0, k1, idx + 1u);
    uint32_t b2 = rnd_bits(one, k0, k1, idx + 2u);
    uint32_t b3 = rnd_bits(one, k0, k1, idx + 3u);
    float4 v;
    v.x = bits_to_normal(b0);
    v.y = bits_to_normal(b1);
    v.z = bits_to_normal(b2);
    v.w = bits_to_normal(b3);
    *(float4*)&g_noise[((size_t)s << 25) + idx] = v;
}

// ===========================================================================
// Precompute per-thread-identity bf16 J fragments (1 CTA, direct LDG)
// g_bfrag[tid*32 + 8*kkPair + ...]: order matches the uint4 loads in lang_step
// ===========================================================================
__global__ void prep_frag(const float* __restrict__ J)
{
    int tid = threadIdx.x, w = tid >> 5, lane = tid & 31;
    int g = lane >> 2, i = lane & 3;
    int N0 = 16 * w;
#pragma unroll
    for (int kk = 0; kk < 8; kk++)
#pragma unroll
        for (int j = 0; j < 2; j++) {
            int c = N0 + 8 * j + g;
            int k0r = 16 * kk + 2 * i;
            float j0 = J[(k0r    ) * 128 + c];
            float j1 = J[(k0r + 1) * 128 + c];
            float j2 = J[(k0r + 8) * 128 + c];
            float j3 = J[(k0r + 9) * 128 + c];
            g_bfrag[tid * 32 + (kk * 2 + j) * 2 + 0] = pack_bf16(j1, j0);
            g_bfrag[tid * 32 + (kk * 2 + j) * 2 + 1] = pack_bf16(j3, j2);
        }
}

// ===========================================================================
// Phase 1 (unchanged — verified rounds 9-11)
// ===========================================================================
__global__ void __launch_bounds__(NTHREADS, 2) phase1_mma(
    const float* __restrict__ x_input, const float* __restrict__ W)
{
    extern __shared__ float sm[];
    uint32_t* smu = (uint32_t*)sm;
    int tid = threadIdx.x, w = tid >> 5, lane = tid & 31;
    int g = lane >> 2, i = lane & 3;
    int N0 = 16 * w;
    int tb = blockIdx.x * 64;

    const float4* W4 = (const float4*)W;
    for (int idx = tid; idx < 4096; idx += NTHREADS) {
        int r = idx >> 5, q = idx & 31;
        *(float4*)&sm[r * PL_ROW + 4 * q] = W4[idx];
    }
    __syncthreads();

    uint32_t Bf[16][2][2];
#pragma unroll
    for (int kk = 0; kk < 16; kk++)
#pragma unroll
        for (int j = 0; j < 2; j++) {
            Bf[kk][j][0] = f2tf32(sm[(8 * kk + i) * PL_ROW + N0 + 8 * j + g]);
            Bf[kk][j][1] = f2tf32(sm[(8 * kk + i + 4) * PL_ROW + N0 + 8 * j + g]);
        }
    __syncthreads();

    const float4* X4 = (const float4*)(x_input + (size_t)tb * 128);
    for (int idx = tid; idx < 2048; idx += NTHREADS) {
        int r = idx >> 5, q = idx & 31;
        float4 v = X4[idx];
        *(float4*)&sm[P1_XST + r * PL_ROW + 4 * q] = v;
        smu[P1_XT + r * XT_ROW + 0 * XT_CLS + q] = f2tf32(v.x);
        smu[P1_XT + r * XT_ROW + 1 * XT_CLS + q] = f2tf32(v.y);
        smu[P1_XT + r * XT_ROW + 2 * XT_CLS + q] = f2tf32(v.z);
        smu[P1_XT + r * XT_ROW + 3 * XT_CLS + q] = f2tf32(v.w);
    }
    __syncthreads();

    int cA = N0 + 2 * i, cB = cA + 8;
    float acc = 0.f;
#pragma unroll 1
    for (int R = 0; R < 4; R++) {
        int r0 = 16 * R + g, r1 = r0 + 8;
        float D0[4] = {0,0,0,0}, D1[4] = {0,0,0,0};
        const uint32_t* xt0 = &smu[P1_XT + r0 * XT_ROW + i * XT_CLS];
        const uint32_t* xt1 = &smu[P1_XT + r1 * XT_ROW + i * XT_CLS];
#pragma unroll
        for (int j = 0; j < 8; j++) {
            uint4 va = *(const uint4*)(xt0 + 4 * j);
            uint4 vb = *(const uint4*)(xt1 + 4 * j);
            uint32_t a[4];
            a[0] = va.x; a[1] = vb.x; a[2] = va.y; a[3] = vb.y;
            mma_tf32(D0, a, Bf[2 * j][0]);
            mma_tf32(D1, a, Bf[2 * j][1]);
            a[0] = va.z; a[1] = vb.z; a[2] = va.w; a[3] = vb.w;
            mma_tf32(D0, a, Bf[2 * j + 1][0]);
            mma_tf32(D1, a, Bf[2 * j + 1][1]);
        }
        float2 x00 = *(float2*)&sm[P1_XST + r0 * PL_ROW + cA];
        float2 x01 = *(float2*)&sm[P1_XST + r0 * PL_ROW + cB];
        float2 x10 = *(float2*)&sm[P1_XST + r1 * PL_ROW + cA];
        float2 x11 = *(float2*)&sm[P1_XST + r1 * PL_ROW + cB];
        float e;
        e = x00.x - tanh_fast(D0[0]); acc = fmaf(e, e, acc);
        e = x00.y - tanh_fast(D0[1]); acc = fmaf(e, e, acc);
        e = x01.x - tanh_fast(D1[0]); acc = fmaf(e, e, acc);
        e = x01.y - tanh_fast(D1[1]); acc = fmaf(e, e, acc);
        e = x10.x - tanh_fast(D0[2]); acc = fmaf(e, e, acc);
        e = x10.y - tanh_fast(D0[3]); acc = fmaf(e, e, acc);
        e = x11.x - tanh_fast(D1[2]); acc = fmaf(e, e, acc);
        e = x11.y - tanh_fast(D1[3]); acc = fmaf(e, e, acc);
    }
    double da = (double)acc;
#pragma unroll
    for (int off = 16; off; off >>= 1)
        da += __shfl_xor_sync(0xffffffffu, da, off);
    __shared__ double sacc[8];
    if (lane == 0) sacc[w] = da;
    __syncthreads();
    if (tid == 0) {
        double t = 0.0;
#pragma unroll
        for (int k = 0; k < 8; k++) t += sacc[k];
        atomicAdd(&g_sum, t);
    }
}

// ===========================================================================
// Langevin step 0: x = tanh(0.1*(xin-h) + ns*noise), pure streaming
// ===========================================================================
__global__ void __launch_bounds__(NTHREADS) lang_step0(
    const float* __restrict__ x_input, const float* __restrict__ h)
{
    float ns = g_noise_scale;
    uint32_t t = blockIdx.x * NTHREADS + threadIdx.x;
    size_t idx = (size_t)t * 4;
    float4 xin = *(const float4*)(x_input + idx);
    float4 hv  = ((const float4*)h)[t & 31];
    float4 nz  = *(const float4*)(g_noise + idx);
    float4 r;
    r.x = tanh_fast(fmaf(nz.x, ns, 0.1f * (xin.x - hv.x)));
    r.y = tanh_fast(fmaf(nz.y, ns, 0.1f * (xin.y - hv.y)));
    r.z = tanh_fast(fmaf(nz.z, ns, 0.1f * (xin.z - hv.z)));
    r.w = tanh_fast(fmaf(nz.w, ns, 0.1f * (xin.w - hv.w)));
    *(float4*)(g_X + idx) = r;
}

// ===========================================================================
// Langevin step s (1..9): bf16 MMA vs previous state, elementwise, store
// ===========================================================================
__global__ void __launch_bounds__(NTHREADS, 2) lang_step(
    const float* __restrict__ x_input, const float* __restrict__ h,
    float* __restrict__ out, int s)
{
    __shared__ uint32_t xt[64 * ROWP];
    int tid = threadIdx.x, w = tid >> 5, lane = tid & 31;
    int g = lane >> 2, i = lane & 3;
    int N0 = 16 * w;
    int tb = blockIdx.x * 64;
    int cA = N0 + 2 * i, cB = cA + 8;
    int sA = 2 * w, sB = sA + 1, xb = CSP * i;
    bool last = (s == STEPS - 1);
    float ns = g_noise_scale;

    // persistent J fragments (coalesced 128B/thread, L2-resident)
    uint32_t Bf[32];
    {
        const uint4* bp = (const uint4*)(g_bfrag + tid * 32);
#pragma unroll
        for (int q = 0; q < 8; q++) {
            uint4 v = bp[q];
            Bf[4 * q + 0] = v.x; Bf[4 * q + 1] = v.y;
            Bf[4 * q + 2] = v.z; Bf[4 * q + 3] = v.w;
        }
    }

    // load X_prev (exact) and stage bf16 XT
    float2 xp[4][4];
#pragma unroll
    for (int R = 0; R < 4; R++) {
        int r0 = 16 * R + g, r1 = r0 + 8;
        xp[R][0] = *(const float2*)(g_X + (size_t)(tb + r0) * 128 + cA);
        xp[R][1] = *(const float2*)(g_X + (size_t)(tb + r0) * 128 + cB);
        xp[R][2] = *(const float2*)(g_X + (size_t)(tb + r1) * 128 + cA);
        xp[R][3] = *(const float2*)(g_X + (size_t)(tb + r1) * 128 + cB);
    }
#pragma unroll
    for (int R = 0; R < 4; R++) {
        int r0 = 16 * R + g, r1 = r0 + 8;
        xt[r0 * ROWP + xb + sA] = pack_bf16(xp[R][0].y, xp[R][0].x);
        xt[r0 * ROWP + xb + sB] = pack_bf16(xp[R][1].y, xp[R][1].x);
        xt[r1 * ROWP + xb + sA] = pack_bf16(xp[R][2].y, xp[R][2].x);
        xt[r1 * ROWP + xb + sB] = pack_bf16(xp[R][3].y, xp[R][3].x);
    }
    __syncthreads();

    const float* nsrc = g_noise + ((size_t)s << 25) + (size_t)tb * 128;
    const float* xsrc = x_input + (size_t)tb * 128;
    float* dst = last ? (out + (size_t)tb * 128) : (g_X + (size_t)tb * 128);
    float2 hA = *(const float2*)(h + cA);
    float2 hB = *(const float2*)(h + cB);

#pragma unroll
    for (int R = 0; R < 4; R++) {
        int r0 = 16 * R + g, r1 = r0 + 8;
        // prefetch noise + x_input (consumed after MMA)
        float2 nz0 = *(const float2*)(nsrc + r0 * 128 + cA);
        float2 nz1 = *(const float2*)(nsrc + r0 * 128 + cB);
        float2 nz2 = *(const float2*)(nsrc + r1 * 128 + cA);
        float2 nz3 = *(const float2*)(nsrc + r1 * 128 + cB);
        float2 xi0 = *(const float2*)(xsrc + r0 * 128 + cA);
        float2 xi1 = *(const float2*)(xsrc + r0 * 128 + cB);
        float2 xi2 = *(const float2*)(xsrc + r1 * 128 + cA);
        float2 xi3 = *(const float2*)(xsrc + r1 * 128 + cB);

        float D0a[4] = {0,0,0,0}, D0b[4] = {0,0,0,0};
        float D1a[4] = {0,0,0,0}, D1b[4] = {0,0,0,0};
        const uint32_t* xt0 = &xt[r0 * ROWP + xb];
        const uint32_t* xt1 = &xt[r1 * ROWP + xb];
#pragma unroll
        for (int j = 0; j < 4; j++) {
            uint4 va = *(const uint4*)(xt0 + 4 * j);
            uint4 vb = *(const uint4*)(xt1 + 4 * j);
            float* D0 = (j < 2) ? D0a : D0b;
            float* D1 = (j < 2) ? D1a : D1b;
            uint32_t a[4];
            a[0] = va.x; a[1] = vb.x; a[2] = va.y; a[3] = vb.y;
            mma_bf16(D0, a, &Bf[8 * j + 0]);
            mma_bf16(D1, a, &Bf[8 * j + 2]);
            a[0] = va.z; a[1] = vb.z; a[2] = va.w; a[3] = vb.w;
            mma_bf16(D0, a, &Bf[8 * j + 4]);
            mma_bf16(D1, a, &Bf[8 * j + 6]);
        }
        float D0[4], D1[4];
#pragma unroll
        for (int q = 0; q < 4; q++) {
            D0[q] = D0a[q] + D0b[q];
            D1[q] = D1a[q] + D1b[q];
        }
        float2 n00, n01, n10, n11;
        n00.x = tanh_fast(fmaf(nz0.x, ns, fmaf(D0[0], -0.1f, fmaf(0.1f, xi0.x - hA.x, xp[R][0].x))));
        n00.y = tanh_fast(fmaf(nz0.y, ns, fmaf(D0[1], -0.1f, fmaf(0.1f, xi0.y - hA.y, xp[R][0].y))));
        n01.x = tanh_fast(fmaf(nz1.x, ns, fmaf(D1[0], -0.1f, fmaf(0.1f, xi1.x - hB.x, xp[R][1].x))));
        n01.y = tanh_fast(fmaf(nz1.y, ns, fmaf(D1[1], -0.1f, fmaf(0.1f, xi1.y - hB.y, xp[R][1].y))));
        n10.x = tanh_fast(fmaf(nz2.x, ns, fmaf(D0[2], -0.1f, fmaf(0.1f, xi2.x - hA.x, xp[R][2].x))));
        n10.y = tanh_fast(fmaf(nz2.y, ns, fmaf(D0[3], -0.1f, fmaf(0.1f, xi2.y - hA.y, xp[R][2].y))));
        n11.x = tanh_fast(fmaf(nz3.x, ns, fmaf(D1[2], -0.1f, fmaf(0.1f, xi3.x - hB.x, xp[R][3].x))));
        n11.y = tanh_fast(fmaf(nz3.y, ns, fmaf(D1[3], -0.1f, fmaf(0.1f, xi3.y - hB.y, xp[R][3].y))));
        *(float2*)(dst + r0 * 128 + cA) = n00;
        *(float2*)(dst + r0 * 128 + cB) = n01;
        *(float2*)(dst + r1 * 128 + cA) = n10;
        *(float2*)(dst + r1 * 128 + cB) = n11;
    }
}

// ===========================================================================
// Launch: forked-stream pipeline (noise || phase1+langevin chain)
// ===========================================================================
extern "C" void kernel_launch(void* const* d_in, const int* in_sizes, int n_in,
                              void* d_out, int out_size)
{
    const float* x_input = (const float*)d_in[0];
    const float* W       = (const float*)d_in[1];
    const float* J       = (const float*)d_in[2];
    const float* h       = (const float*)d_in[3];
    float* out           = (float*)d_out;

    Keys keys;
    for (int s = 0; s < STEPS; s++) {
        uint32_t o0, o1;
        threefry_host(0u, 1u, 0u, (uint32_t)s, o0, o1);
        keys.k0[s] = o0;
        keys.k1[s] = o1;
    }
    keys.one = 1u;

    static cudaStream_t s2 = nullptr;
    static cudaEvent_t evFork, evN[STEPS];
    if (!s2) {
        cudaStreamCreateWithFlags(&s2, cudaStreamNonBlocking);
        cudaEventCreateWithFlags(&evFork, cudaEventDisableTiming);
        for (int s = 0; s < STEPS; s++)
            cudaEventCreateWithFlags(&evN[s], cudaEventDisableTiming);
        cudaFuncSetAttribute(phase1_mma,
            cudaFuncAttributeMaxDynamicSharedMemorySize, P1_SMEM);
    }

    const int NB_STREAM = (int)(N_ELEM / 4 / NTHREADS);  // 32768

    // fork: noise chain on s2 (no dependency on nscale — unscaled normals)
    cudaEventRecord(evFork, 0);
    cudaStreamWaitEvent(s2, evFork, 0);
    for (int s = 0; s < STEPS; s++) {
        noise_step<<<NB_STREAM, NTHREADS, 0, s2>>>(keys, s);
        cudaEventRecord(evN[s], s2);
    }

    // main chain on default stream
    zero_kernel<<<1, 1>>>();
    prep_frag<<<1, NTHREADS>>>(J);
    phase1_mma<<<B_ROWS / 64, NTHREADS, P1_SMEM>>>(x_input, W);
    finalize_kernel<<<1, 1>>>();

    cudaStreamWaitEvent(0, evN[0], 0);
    lang_step0<<<NB_STREAM, NTHREADS>>>(x_input, h);
    for (int s = 1; s < STEPS; s++) {
        cudaStreamWaitEvent(0, evN[s], 0);
        lang_step<<<B_ROWS / 64, NTHREADS>>>(x_input, h, out, s);
    }
}

// round 13
// speedup vs baseline: 1.3470x; 1.3470x over previous
#include <cuda_runtime.h>
#include <cstdint>
#include <math.h>

#define B_ROWS   262144
#define STEPS    10
#define NTHREADS 256

__device__ double g_sum;
__device__ float  g_noise_scale;

// ---- phase1 SMEM layout ----
#define XT_ROW 164
#define XT_CLS 40
#define PL_ROW 132
#define P1_XT  0
#define P1_XST (64*XT_ROW)
#define P1_WORDS (P1_XST + 64*PL_ROW)
#define P1_SMEM (P1_WORDS*4)

// ---- langevin SMEM layout (words): XT double buffer + XEX only ----
#define CSP  20
#define ROWP 80
#define XTB  (64*ROWP)          // 5120 words per buffer
#define LG_XT0 0
#define LG_XT1 XTB
#define LG_XEX (2*XTB)          // 10240
#define LG_WORDS (LG_XEX + 64*PL_ROW)   // 18688 words
#define LG_SMEM (LG_WORDS*4)            // 74752 B -> 3 CTAs/SM
// J is staged over words [0, 16896) before step 0 (dead after Bf extraction)

// ---------------------------------------------------------------------------
// MMA helpers
// ---------------------------------------------------------------------------
__device__ __forceinline__ uint32_t f2tf32(float f) {
    uint32_t r;
    asm("cvt.rna.tf32.f32 %0, %1;" : "=r"(r) : "f"(f));
    return r;
}
__device__ __forceinline__ void mma_tf32(float d[4], const uint32_t a[4],
                                         const uint32_t b[2]) {
    asm volatile(
        "mma.sync.aligned.m16n8k8.row.col.f32.tf32.tf32.f32 "
        "{%0,%1,%2,%3}, {%4,%5,%6,%7}, {%8,%9}, {%0,%1,%2,%3};\n"
        : "+f"(d[0]), "+f"(d[1]), "+f"(d[2]), "+f"(d[3])
        : "r"(a[0]), "r"(a[1]), "r"(a[2]), "r"(a[3]), "r"(b[0]), "r"(b[1]));
}
__device__ __forceinline__ void mma_bf16(float d[4], const uint32_t a[4],
                                         const uint32_t b[2]) {
    asm volatile(
        "mma.sync.aligned.m16n8k16.row.col.f32.bf16.bf16.f32 "
        "{%0,%1,%2,%3}, {%4,%5,%6,%7}, {%8,%9}, {%0,%1,%2,%3};\n"
        : "+f"(d[0]), "+f"(d[1]), "+f"(d[2]), "+f"(d[3])
        : "r"(a[0]), "r"(a[1]), "r"(a[2]), "r"(a[3]), "r"(b[0]), "r"(b[1]));
}
__device__ __forceinline__ uint32_t pack_bf16(float hi, float lo) {
    uint32_t r;
    asm("cvt.rn.bf16x2.f32 %0, %1, %2;" : "=r"(r) : "f"(hi), "f"(lo));
    return r;
}
__device__ __forceinline__ float tanh_fast(float x) {
    float r;
    asm("tanh.approx.f32 %0, %1;" : "=f"(r) : "f"(x));
    return r;
}
__device__ __forceinline__ uint32_t imad1(uint32_t a, uint32_t one, uint32_t b) {
    uint32_t r;
    asm("mad.lo.u32 %0, %1, %2, %3;" : "=r"(r) : "r"(a), "r"(one), "r"(b));
    return r;
}

// ---------------------------------------------------------------------------
// Threefry-2x32/20
// ---------------------------------------------------------------------------
__host__ __forceinline__ void threefry_host(
    uint32_t k0, uint32_t k1, uint32_t x0, uint32_t x1,
    uint32_t& o0, uint32_t& o1)
{
    uint32_t ks0 = k0, ks1 = k1, ks2 = k0 ^ k1 ^ 0x1BD11BDAu;
    x0 += ks0; x1 += ks1;
#define TF_R(r) { x0 += x1; x1 = (x1 << (r)) | (x1 >> (32 - (r))); x1 ^= x0; }
    TF_R(13) TF_R(15) TF_R(26) TF_R(6)
    x0 += ks1; x1 += ks2 + 1u;
    TF_R(17) TF_R(29) TF_R(16) TF_R(24)
    x0 += ks2; x1 += ks0 + 2u;
    TF_R(13) TF_R(15) TF_R(26) TF_R(6)
    x0 += ks0; x1 += ks1 + 3u;
    TF_R(17) TF_R(29) TF_R(16) TF_R(24)
    x0 += ks1; x1 += ks2 + 4u;
    TF_R(13) TF_R(15) TF_R(26) TF_R(6)
    x0 += ks2; x1 += ks0 + 5u;
#undef TF_R
    o0 = x0; o1 = x1;
}

// Device: x0-chain IMAD (fma pipe), x1-chain alu; bits = o0^o1, counter (0,idx)
__device__ __forceinline__ uint32_t rnd_bits(uint32_t one,
    uint32_t k0, uint32_t k1, uint32_t idx)
{
    uint32_t ks2 = k0 ^ k1 ^ 0x1BD11BDAu;
    uint32_t x0 = k0;
    uint32_t x1 = idx + k1;
#define TF_B(r) { x0 = imad1(x0, one, x1); x1 = __funnelshift_l(x1, x1, r); x1 ^= x0; }
    TF_B(13) TF_B(15) TF_B(26) TF_B(6)
    x0 = imad1(x0, one, k1);  x1 += ks2 + 1u;
    TF_B(17) TF_B(29) TF_B(16) TF_B(24)
    x0 = imad1(x0, one, ks2); x1 += k0 + 2u;
    TF_B(13) TF_B(15) TF_B(26) TF_B(6)
    x0 = imad1(x0, one, k0);  x1 += k1 + 3u;
    TF_B(17) TF_B(29) TF_B(16) TF_B(24)
    x0 = imad1(x0, one, k1);  x1 += ks2 + 4u;
    TF_B(13) TF_B(15) TF_B(26) TF_B(6)
    x0 = imad1(x0, one, ks2); x1 += k0 + 5u;
#undef TF_B
    return x0 ^ x1;
}

__device__ __forceinline__ float bits_to_normal(uint32_t bits)
{
    const float lo = -0.99999994f;
    float u = __uint_as_float((bits >> 9) | 0x3f800000u) - 1.0f;
    float x = fmaf(u, 2.0f, lo);
    x = fmaxf(x, lo);
    float w = -__logf(fmaf(-x, x, 1.0f));
    float p;
    if (w < 5.0f) {
        w -= 2.5f;
        p = 2.81022636e-08f;
        p = fmaf(p, w, 3.43273939e-07f);
        p = fmaf(p, w, -3.5233877e-06f);
        p = fmaf(p, w, -4.39150654e-06f);
        p = fmaf(p, w, 0.00021858087f);
        p = fmaf(p, w, -0.00125372503f);
        p = fmaf(p, w, -0.00417768164f);
        p = fmaf(p, w, 0.246640727f);
        p = fmaf(p, w, 1.50140941f);
    } else {
        w = sqrtf(w) - 3.0f;
        p = -0.000200214257f;
        p = fmaf(p, w, 0.000100950558f);
        p = fmaf(p, w, 0.00134934322f);
        p = fmaf(p, w, -0.00367342844f);
        p = fmaf(p, w, 0.00573950773f);
        p = fmaf(p, w, -0.0076224613f);
        p = fmaf(p, w, 0.00943887047f);
        p = fmaf(p, w, 1.00167406f);
        p = fmaf(p, w, 2.83297682f);
    }
    return 1.41421354f * (p * x);
}

struct Keys { uint32_t k0[STEPS]; uint32_t k1[STEPS]; uint32_t one; };

__global__ void zero_kernel() { g_sum = 0.0; }
__global__ void finalize_kernel()
{
    double mean = g_sum * (1.0 / 33554432.0);
    float temp = 0.1f * (1.0f + (float)mean * 10.0f);
    g_noise_scale = sqrtf(2.0f * 0.1f * temp);
}

// x' = tanh( ns*nrm + (xp + (0.1*xi + mh)) - 0.1*d )
__device__ __forceinline__ float2 elw2x(uint32_t one, float d0, float d1,
    float2 xp, float2 xi, float2 mh, uint32_t row_g, uint32_t col0,
    uint32_t kk0, uint32_t kk1, float ns)
{
    uint32_t base = row_g * 128u + col0;
    float n0 = bits_to_normal(rnd_bits(one, kk0, kk1, base));
    float n1 = bits_to_normal(rnd_bits(one, kk0, kk1, base + 1u));
    float2 r;
    float u0 = xp.x + fmaf(0.1f, xi.x, mh.x);
    float u1 = xp.y + fmaf(0.1f, xi.y, mh.y);
    r.x = tanh_fast(fmaf(n0, ns, fmaf(d0, -0.1f, u0)));
    r.y = tanh_fast(fmaf(n1, ns, fmaf(d1, -0.1f, u1)));
    return r;
}

// ===========================================================================
// Phase 1 (unchanged — verified rounds 9-12)
// ===========================================================================
__global__ void __launch_bounds__(NTHREADS, 2) phase1_mma(
    const float* __restrict__ x_input, const float* __restrict__ W)
{
    extern __shared__ float sm[];
    uint32_t* smu = (uint32_t*)sm;
    int tid = threadIdx.x, w = tid >> 5, lane = tid & 31;
    int g = lane >> 2, i = lane & 3;
    int N0 = 16 * w;
    int tb = blockIdx.x * 64;

    const float4* W4 = (const float4*)W;
    for (int idx = tid; idx < 4096; idx += NTHREADS) {
        int r = idx >> 5, q = idx & 31;
        *(float4*)&sm[r * PL_ROW + 4 * q] = W4[idx];
    }
    __syncthreads();

    uint32_t Bf[16][2][2];
#pragma unroll
    for (int kk = 0; kk < 16; kk++)
#pragma unroll
        for (int j = 0; j < 2; j++) {
            Bf[kk][j][0] = f2tf32(sm[(8 * kk + i) * PL_ROW + N0 + 8 * j + g]);
            Bf[kk][j][1] = f2tf32(sm[(8 * kk + i + 4) * PL_ROW + N0 + 8 * j + g]);
        }
    __syncthreads();

    const float4* X4 = (const float4*)(x_input + (size_t)tb * 128);
    for (int idx = tid; idx < 2048; idx += NTHREADS) {
        int r = idx >> 5, q = idx & 31;
        float4 v = X4[idx];
        *(float4*)&sm[P1_XST + r * PL_ROW + 4 * q] = v;
        smu[P1_XT + r * XT_ROW + 0 * XT_CLS + q] = f2tf32(v.x);
        smu[P1_XT + r * XT_ROW + 1 * XT_CLS + q] = f2tf32(v.y);
        smu[P1_XT + r * XT_ROW + 2 * XT_CLS + q] = f2tf32(v.z);
        smu[P1_XT + r * XT_ROW + 3 * XT_CLS + q] = f2tf32(v.w);
    }
    __syncthreads();

    int cA = N0 + 2 * i, cB = cA + 8;
    float acc = 0.f;
#pragma unroll 1
    for (int R = 0; R < 4; R++) {
        int r0 = 16 * R + g, r1 = r0 + 8;
        float D0[4] = {0,0,0,0}, D1[4] = {0,0,0,0};
        const uint32_t* xt0 = &smu[P1_XT + r0 * XT_ROW + i * XT_CLS];
        const uint32_t* xt1 = &smu[P1_XT + r1 * XT_ROW + i * XT_CLS];
#pragma unroll
        for (int j = 0; j < 8; j++) {
            uint4 va = *(const uint4*)(xt0 + 4 * j);
            uint4 vb = *(const uint4*)(xt1 + 4 * j);
            uint32_t a[4];
            a[0] = va.x; a[1] = vb.x; a[2] = va.y; a[3] = vb.y;
            mma_tf32(D0, a, Bf[2 * j][0]);
            mma_tf32(D1, a, Bf[2 * j][1]);
            a[0] = va.z; a[1] = vb.z; a[2] = va.w; a[3] = vb.w;
            mma_tf32(D0, a, Bf[2 * j + 1][0]);
            mma_tf32(D1, a, Bf[2 * j + 1][1]);
        }
        float2 x00 = *(float2*)&sm[P1_XST + r0 * PL_ROW + cA];
        float2 x01 = *(float2*)&sm[P1_XST + r0 * PL_ROW + cB];
        float2 x10 = *(float2*)&sm[P1_XST + r1 * PL_ROW + cA];
        float2 x11 = *(float2*)&sm[P1_XST + r1 * PL_ROW + cB];
        float e;
        e = x00.x - tanh_fast(D0[0]); acc = fmaf(e, e, acc);
        e = x00.y - tanh_fast(D0[1]); acc = fmaf(e, e, acc);
        e = x01.x - tanh_fast(D1[0]); acc = fmaf(e, e, acc);
        e = x01.y - tanh_fast(D1[1]); acc = fmaf(e, e, acc);
        e = x10.x - tanh_fast(D0[2]); acc = fmaf(e, e, acc);
        e = x10.y - tanh_fast(D0[3]); acc = fmaf(e, e, acc);
        e = x11.x - tanh_fast(D1[2]); acc = fmaf(e, e, acc);
        e = x11.y - tanh_fast(D1[3]); acc = fmaf(e, e, acc);
    }
    double da = (double)acc;
#pragma unroll
    for (int off = 16; off; off >>= 1)
        da += __shfl_xor_sync(0xffffffffu, da, off);
    __shared__ double sacc[8];
    if (lane == 0) sacc[w] = da;
    __syncthreads();
    if (tid == 0) {
        double t = 0.0;
#pragma unroll
        for (int k = 0; k < 8; k++) t += sacc[k];
        atomicAdd(&g_sum, t);
    }
}

// ===========================================================================
// Langevin: fused PRNG + bf16 MMA, double-buffered XT, NO C buffer,
// 3 CTAs/SM. x_input re-read from L2 each step; h folded into registers.
// ===========================================================================
__global__ void __launch_bounds__(NTHREADS, 3) langevin_bf16(
    const float* __restrict__ x_input, const float* __restrict__ J,
    const float* __restrict__ h, float* __restrict__ out, Keys keys)
{
    extern __shared__ float sm[];
    uint32_t* smu = (uint32_t*)sm;
    int tid = threadIdx.x, w = tid >> 5, lane = tid & 31;
    int g = lane >> 2, i = lane & 3;
    int N0 = 16 * w;
    int tb = blockIdx.x * 64;
    uint32_t one = keys.one;

    // stage J [128x128] over the XT/XEX union (dead until step 0 writes)
    const float4* J4 = (const float4*)J;
    for (int idx = tid; idx < 4096; idx += NTHREADS) {
        int r = idx >> 5, q = idx & 31;
        *(float4*)&sm[r * PL_ROW + 4 * q] = J4[idx];
    }
    __syncthreads();

    uint32_t Bf[8][2][2];
#pragma unroll
    for (int kk = 0; kk < 8; kk++)
#pragma unroll
        for (int j = 0; j < 2; j++) {
            int c = N0 + 8 * j + g;
            int k0r = 16 * kk + 2 * i;
            float j0 = sm[(k0r    ) * PL_ROW + c];
            float j1 = sm[(k0r + 1) * PL_ROW + c];
            float j2 = sm[(k0r + 8) * PL_ROW + c];
            float j3 = sm[(k0r + 9) * PL_ROW + c];
            Bf[kk][j][0] = pack_bf16(j1, j0);
            Bf[kk][j][1] = pack_bf16(j3, j2);
        }
    __syncthreads();

    float ns = g_noise_scale;
    int cA = N0 + 2 * i, cB = cA + 8;
    int sA = 2 * w, sB = 2 * w + 1;
    int xbase = CSP * i;
    const float* xsrc = x_input + (size_t)tb * 128;

    // mh = -0.1*h at this thread's columns
    float2 hA = *(const float2*)(h + cA);
    float2 hB = *(const float2*)(h + cB);
    float2 mhA = make_float2(-0.1f * hA.x, -0.1f * hA.y);
    float2 mhB = make_float2(-0.1f * hB.x, -0.1f * hB.y);

    // ---- step 0: x = 0, d = 0 ----
    {
        uint32_t kk0 = keys.k0[0], kk1 = keys.k1[0];
        float2 z = make_float2(0.f, 0.f);
#pragma unroll
        for (int R = 0; R < 4; R++) {
            int r0 = 16 * R + g, r1 = r0 + 8;
            float2 xi0 = *(const float2*)(xsrc + r0 * 128 + cA);
            float2 xi1 = *(const float2*)(xsrc + r0 * 128 + cB);
            float2 xi2 = *(const float2*)(xsrc + r1 * 128 + cA);
            float2 xi3 = *(const float2*)(xsrc + r1 * 128 + cB);
            float2 n00 = elw2x(one, 0.f, 0.f, z, xi0, mhA, tb + r0, cA, kk0, kk1, ns);
            float2 n01 = elw2x(one, 0.f, 0.f, z, xi1, mhB, tb + r0, cB, kk0, kk1, ns);
            float2 n10 = elw2x(one, 0.f, 0.f, z, xi2, mhA, tb + r1, cA, kk0, kk1, ns);
            float2 n11 = elw2x(one, 0.f, 0.f, z, xi3, mhB, tb + r1, cB, kk0, kk1, ns);
            *(float2*)&sm[LG_XEX + r0 * PL_ROW + cA] = n00;
            *(float2*)&sm[LG_XEX + r0 * PL_ROW + cB] = n01;
            *(float2*)&sm[LG_XEX + r1 * PL_ROW + cA] = n10;
            *(float2*)&sm[LG_XEX + r1 * PL_ROW + cB] = n11;
            smu[LG_XT0 + r0 * ROWP + xbase + sA] = pack_bf16(n00.y, n00.x);
            smu[LG_XT0 + r0 * ROWP + xbase + sB] = pack_bf16(n01.y, n01.x);
            smu[LG_XT0 + r1 * ROWP + xbase + sA] = pack_bf16(n10.y, n10.x);
            smu[LG_XT0 + r1 * ROWP + xbase + sB] = pack_bf16(n11.y, n11.x);
        }
    }
    __syncthreads();

    // ---- steps 1..9: read XT[(s-1)&1], write XT[s&1]; 1 barrier/step ----
#pragma unroll 1
    for (int s = 1; s < STEPS; s++) {
        uint32_t kk0 = keys.k0[s], kk1 = keys.k1[s];
        bool lastS = (s == STEPS - 1);
        int xtR = ((s - 1) & 1) ? LG_XT1 : LG_XT0;
        int xtW = (s & 1) ? LG_XT1 : LG_XT0;
#pragma unroll
        for (int R = 0; R < 4; R++) {
            int r0 = 16 * R + g, r1 = r0 + 8;
            // x_input reloads (L2-resident), issued early
            float2 xi0 = *(const float2*)(xsrc + r0 * 128 + cA);
            float2 xi1 = *(const float2*)(xsrc + r0 * 128 + cB);
            float2 xi2 = *(const float2*)(xsrc + r1 * 128 + cA);
            float2 xi3 = *(const float2*)(xsrc + r1 * 128 + cB);
            float D0[4] = {0,0,0,0}, D1[4] = {0,0,0,0};
            const uint32_t* xt0 = &smu[xtR + r0 * ROWP + xbase];
            const uint32_t* xt1 = &smu[xtR + r1 * ROWP + xbase];
#pragma unroll
            for (int j = 0; j < 4; j++) {
                uint4 va = *(const uint4*)(xt0 + 4 * j);
                uint4 vb = *(const uint4*)(xt1 + 4 * j);
                uint32_t a[4];
                a[0] = va.x; a[1] = vb.x; a[2] = va.y; a[3] = vb.y;
                mma_bf16(D0, a, Bf[2 * j][0]);
                mma_bf16(D1, a, Bf[2 * j][1]);
                a[0] = va.z; a[1] = vb.z; a[2] = va.w; a[3] = vb.w;
                mma_bf16(D0, a, Bf[2 * j + 1][0]);
                mma_bf16(D1, a, Bf[2 * j + 1][1]);
            }
            float2 xo00 = *(float2*)&sm[LG_XEX + r0 * PL_ROW + cA];
            float2 xo01 = *(float2*)&sm[LG_XEX + r0 * PL_ROW + cB];
            float2 xo10 = *(float2*)&sm[LG_XEX + r1 * PL_ROW + cA];
            float2 xo11 = *(float2*)&sm[LG_XEX + r1 * PL_ROW + cB];
            float2 n00 = elw2x(one, D0[0], D0[1], xo00, xi0, mhA, tb + r0, cA, kk0, kk1, ns);
            float2 n01 = elw2x(one, D1[0], D1[1], xo01, xi1, mhB, tb + r0, cB, kk0, kk1, ns);
            float2 n10 = elw2x(one, D0[2], D0[3], xo10, xi2, mhA, tb + r1, cA, kk0, kk1, ns);
            float2 n11 = elw2x(one, D1[2], D1[3], xo11, xi3, mhB, tb + r1, cB, kk0, kk1, ns);
            *(float2*)&sm[LG_XEX + r0 * PL_ROW + cA] = n00;
            *(float2*)&sm[LG_XEX + r0 * PL_ROW + cB] = n01;
            *(float2*)&sm[LG_XEX + r1 * PL_ROW + cA] = n10;
            *(float2*)&sm[LG_XEX + r1 * PL_ROW + cB] = n11;
            if (!lastS) {
                smu[xtW + r0 * ROWP + xbase + sA] = pack_bf16(n00.y, n00.x);
                smu[xtW + r0 * ROWP + xbase + sB] = pack_bf16(n01.y, n01.x);
                smu[xtW + r1 * ROWP + xbase + sA] = pack_bf16(n10.y, n10.x);
                smu[xtW + r1 * ROWP + xbase + sB] = pack_bf16(n11.y, n11.x);
            }
        }
        __syncthreads();
    }

    // output copy, coalesced
    float4* o4 = (float4*)(out + (size_t)tb * 128);
    for (int idx = tid; idx < 2048; idx += NTHREADS) {
        int r = idx >> 5, q = idx & 31;
        o4[idx] = *(float4*)&sm[LG_XEX + r * PL_ROW + 4 * q];
    }
}

// ===========================================================================
// Launch
// ===========================================================================
extern "C" void kernel_launch(void* const* d_in, const int* in_sizes, int n_in,
                              void* d_out, int out_size)
{
    const float* x_input = (const float*)d_in[0];
    const float* W       = (const float*)d_in[1];
    const float* J       = (const float*)d_in[2];
    const float* h       = (const float*)d_in[3];
    float* out           = (float*)d_out;

    Keys keys;
    for (int s = 0; s < STEPS; s++) {
        uint32_t o0, o1;
        threefry_host(0u, 1u, 0u, (uint32_t)s, o0, o1);
        keys.k0[s] = o0;
        keys.k1[s] = o1;
    }
    keys.one = 1u;

    static bool attr_set = false;
    if (!attr_set) {
        cudaFuncSetAttribute(phase1_mma,
            cudaFuncAttributeMaxDynamicSharedMemorySize, P1_SMEM);
        cudaFuncSetAttribute(langevin_bf16,
            cudaFuncAttributeMaxDynamicSharedMemorySize, LG_SMEM);
        attr_set = true;
    }

    const int NT = B_ROWS / 64;
    zero_kernel<<<1, 1>>>();
    phase1_mma<<<NT, NTHREADS, P1_SMEM>>>(x_input, W);
    finalize_kernel<<<1, 1>>>();
    langevin_bf16<<<NT, NTHREADS, LG_SMEM>>>(x_input, J, h, out, keys);
}